// round 10
// baseline (speedup 1.0000x reference)
#include <cuda_runtime.h>
#include <cstdint>

#define D_MODEL 1024
#define NB 4
#define NCTA 128
#define NTHREADS 256          // 2 groups x 4 warps; warp handles 2 rows
#define TP1_MAX 2049
#define BOS 0

typedef unsigned long long u64;

// Tagged hidden state: one 64-bit word per element = {tag:32 | value_bits:32}.
// Producer of h_t stores tag = t+1 in the SAME 8-byte scalar relaxed-atomic
// store as the value (single-copy atomic -> no tearing, proven R8).
// Double-buffered by t&1.
__device__ u64 g_hbuf2[2][NB][D_MODEL];

__global__ void rnn_init_kernel() {
    int i = blockIdx.x * blockDim.x + threadIdx.x;
    if (i < 2 * NB * D_MODEL)
        reinterpret_cast<u64*>(g_hbuf2)[i] = 0ull;   // tag 0 == h_{-1}
}

__device__ __forceinline__ u64 ld_relaxed_u64(const u64* p) {
    u64 v;
    asm volatile("ld.relaxed.gpu.global.u64 %0, [%1];" : "=l"(v) : "l"(p) : "memory");
    return v;
}
__device__ __forceinline__ void st_relaxed_u64(u64* p, u64 v) {
    asm volatile("st.relaxed.gpu.global.u64 [%0], %1;" :: "l"(p), "l"(v) : "memory");
}
__device__ __forceinline__ void bar_group(int id) {
    asm volatile("bar.sync %0, 128;" :: "r"(id) : "memory");
}

// Persistent kernel: 128 CTAs x 8 rows. The CTA splits into TWO INDEPENDENT
// 4-warp groups: group 0 (threads 0-127) runs batches {0,1}, group 1 runs
// batches {2,3}. No shared data between groups -> named barriers only; the
// two pipelines overlap on the SMSPs, hiding each other's stalls.
// Each warp owns 2 rows (64 W floats/lane) and reads h once for both.
// PUBLISH-EARLY: h of unit v-1 is kept in lane0 registers across the barrier
// and stored at the TOP of iteration v, giving peer CTAs a full iteration of
// store->visible slack before their tag check (the R9 failure mode, fixed).
__global__ void __launch_bounds__(NTHREADS, 1)
rnn_scan_kernel(const int*   __restrict__ ids,
                const float* __restrict__ emb,
                const float* __restrict__ W,
                float*       __restrict__ out,
                int Tp1)
{
    __shared__ unsigned short ids_sm[NB * TP1_MAX];   // tokens incl. BOS (vocab<65536)
    __shared__ float4 hsm[2][2][D_MODEL / 4];         // [group][buf][...]

    const int tid  = threadIdx.x;
    const int lane = tid & 31;
    const int w    = tid >> 5;
    const int g    = w >> 2;          // group 0/1
    const int wg   = w & 3;           // warp in group
    const int gt   = tid & 127;       // thread in group
    const int r0   = blockIdx.x * 8 + 2 * wg;
    const int r1   = r0 + 1;
    const int gb0  = 2 * g;           // this group's batches
    const int gb1  = 2 * g + 1;

    // ---- W rows -> registers: 2 rows x 32 floats/lane ----
    const float4* __restrict__ Wv = reinterpret_cast<const float4*>(W);
    float4 wr0[8], wr1[8];
#pragma unroll
    for (int k = 0; k < 8; ++k) {
        wr0[k] = Wv[(size_t)r0 * 256 + lane + 32 * k];
        wr1[k] = Wv[(size_t)r1 * 256 + lane + 32 * k];
    }

    // ---- stage token ids with BOS prepended ----
    const int T = Tp1 - 1;
    for (int i = tid; i < NB * Tp1; i += NTHREADS) {
        int b = i / Tp1;
        int t = i - b * Tp1;
        ids_sm[i] = (unsigned short)((t == 0) ? BOS : ids[b * T + (t - 1)]);
    }
    {   // zero input of unit 0 per group
        float4 z = make_float4(0.f, 0.f, 0.f, 0.f);
        hsm[g][0][2 * gt]     = z;
        hsm[g][0][2 * gt + 1] = z;
    }
    __syncthreads();

    // ---- embedding prefetch (lane0): e0 = step t, e1 = step t+1 ----
    // layout: e[j*2 + i] = emb[tok(batch gb_j, t)][r_i]
    float e0[4], e1[4];
    if (lane == 0) {
        int k00 = ids_sm[gb0 * Tp1 + 0], k10 = ids_sm[gb1 * Tp1 + 0];
        e0[0] = emb[(size_t)k00 * D_MODEL + r0];
        e0[1] = emb[(size_t)k00 * D_MODEL + r1];
        e0[2] = emb[(size_t)k10 * D_MODEL + r0];
        e0[3] = emb[(size_t)k10 * D_MODEL + r1];
        if (Tp1 > 1) {
            int k01 = ids_sm[gb0 * Tp1 + 1], k11 = ids_sm[gb1 * Tp1 + 1];
            e1[0] = emb[(size_t)k01 * D_MODEL + r0];
            e1[1] = emb[(size_t)k01 * D_MODEL + r1];
            e1[2] = emb[(size_t)k11 * D_MODEL + r0];
            e1[3] = emb[(size_t)k11 * D_MODEL + r1];
        }
    }

    const int VMAX = 2 * Tp1;          // group-iterations: (t, j) j=batch-in-group
    u64 pk0 = 0, pk1 = 0;              // pending publish (unit v-1), lane0 only

    for (int v = 0; v < VMAX; ++v) {
        const int t  = v >> 1;
        const int j  = v & 1;
        const int bu = 2 * g + j;

        // ---- A. PUBLISH-EARLY: store h of unit v-1 (values held in regs) ----
        if (lane == 0 && v > 0) {
            const int tp = (v - 1) >> 1;
            const int bp = 2 * g + ((v - 1) & 1);
            st_relaxed_u64(&g_hbuf2[tp & 1][bp][r0], pk0);
            st_relaxed_u64(&g_hbuf2[tp & 1][bp][r1], pk1);
        }

        // ---- B. issue tagged stage loads for unit v+1's input ----
        const bool have_next = (v + 1 < VMAX);
        const u64* sp = nullptr;
        u64 s0, s1, s2, s3, s4, s5, s6, s7;
        unsigned exp = 0;
        if (have_next) {
            const int tn = (v + 1) >> 1;
            const int bn = 2 * g + ((v + 1) & 1);
            const int slot = (tn + 1) & 1;           // h_{tn-1} lives here
            sp  = &g_hbuf2[slot][bn][8 * gt];
            exp = (unsigned)tn;
            s0 = ld_relaxed_u64(sp + 0); s1 = ld_relaxed_u64(sp + 1);
            s2 = ld_relaxed_u64(sp + 2); s3 = ld_relaxed_u64(sp + 3);
            s4 = ld_relaxed_u64(sp + 4); s5 = ld_relaxed_u64(sp + 5);
            s6 = ld_relaxed_u64(sp + 6); s7 = ld_relaxed_u64(sp + 7);
        }

        // ---- C. matvec: 2 rows per warp, h read once ----
        const float4* __restrict__ h4 = hsm[g][v & 1];
        float a0 = 0.f, a1 = 0.f, c0 = 0.f, c1 = 0.f;
#pragma unroll
        for (int k = 0; k < 8; ++k) {
            float4 hv = h4[lane + 32 * k];
            if (k < 4) {
                a0 += wr0[k].x * hv.x; a0 += wr0[k].y * hv.y;
                a0 += wr0[k].z * hv.z; a0 += wr0[k].w * hv.w;
                c0 += wr1[k].x * hv.x; c0 += wr1[k].y * hv.y;
                c0 += wr1[k].z * hv.z; c0 += wr1[k].w * hv.w;
            } else {
                a1 += wr0[k].x * hv.x; a1 += wr0[k].y * hv.y;
                a1 += wr0[k].z * hv.z; a1 += wr0[k].w * hv.w;
                c1 += wr1[k].x * hv.x; c1 += wr1[k].y * hv.y;
                c1 += wr1[k].z * hv.z; c1 += wr1[k].w * hv.w;
            }
        }
        float a = a0 + a1;
        float c = c0 + c1;
#pragma unroll
        for (int off = 16; off > 0; off >>= 1) {
            a += __shfl_xor_sync(0xffffffffu, a, off);
            c += __shfl_xor_sync(0xffffffffu, c, off);
        }

        // ---- D. epilogue: h_t rows r0,r1 of batch bu; defer gmem publish ----
        if (lane == 0) {
            float va = a + e0[j * 2 + 0];
            float vc = c + e0[j * 2 + 1];
            out[((size_t)bu * Tp1 + t) * D_MODEL + r0] = va;
            out[((size_t)bu * Tp1 + t) * D_MODEL + r1] = vc;
            const u64 tg = (u64)(unsigned)(t + 1) << 32;
            pk0 = tg | (u64)__float_as_uint(va);
            pk1 = tg | (u64)__float_as_uint(vc);
            if (j == 1) {                        // end of step t: rotate e
                e0[0] = e1[0]; e0[1] = e1[1]; e0[2] = e1[2]; e0[3] = e1[3];
                if (t + 2 < Tp1) {               // prefetch step t+2 (2 iters away)
                    int ka = ids_sm[gb0 * Tp1 + t + 2];
                    int kb = ids_sm[gb1 * Tp1 + t + 2];
                    e1[0] = emb[(size_t)ka * D_MODEL + r0];
                    e1[1] = emb[(size_t)ka * D_MODEL + r1];
                    e1[2] = emb[(size_t)kb * D_MODEL + r0];
                    e1[3] = emb[(size_t)kb * D_MODEL + r1];
                }
            }
        }

        // ---- E. tag check (the ONLY wait) + publish stage to smem ----
        if (have_next) {
            while ((unsigned)(s0 >> 32) != exp || (unsigned)(s1 >> 32) != exp ||
                   (unsigned)(s2 >> 32) != exp || (unsigned)(s3 >> 32) != exp ||
                   (unsigned)(s4 >> 32) != exp || (unsigned)(s5 >> 32) != exp ||
                   (unsigned)(s6 >> 32) != exp || (unsigned)(s7 >> 32) != exp) {
                s0 = ld_relaxed_u64(sp + 0); s1 = ld_relaxed_u64(sp + 1);
                s2 = ld_relaxed_u64(sp + 2); s3 = ld_relaxed_u64(sp + 3);
                s4 = ld_relaxed_u64(sp + 4); s5 = ld_relaxed_u64(sp + 5);
                s6 = ld_relaxed_u64(sp + 6); s7 = ld_relaxed_u64(sp + 7);
            }
            hsm[g][(v + 1) & 1][2 * gt] =
                make_float4(__uint_as_float((unsigned)s0),
                            __uint_as_float((unsigned)s1),
                            __uint_as_float((unsigned)s2),
                            __uint_as_float((unsigned)s3));
            hsm[g][(v + 1) & 1][2 * gt + 1] =
                make_float4(__uint_as_float((unsigned)s4),
                            __uint_as_float((unsigned)s5),
                            __uint_as_float((unsigned)s6),
                            __uint_as_float((unsigned)s7));
        }

        // ---- F. group-scoped named barrier ----
        bar_group(1 + g);
    }
}

extern "C" void kernel_launch(void* const* d_in, const int* in_sizes, int n_in,
                              void* d_out, int out_size) {
    const int*   ids = (const int*)d_in[0];
    const float* emb = (const float*)d_in[1];
    const float* W   = (const float*)d_in[2];
    float* out = (float*)d_out;

    int Tp1 = out_size / (NB * D_MODEL);   // 2049 for the reference shapes
    if (Tp1 > TP1_MAX) Tp1 = TP1_MAX;

    rnn_init_kernel<<<32, 256>>>();
    rnn_scan_kernel<<<NCTA, NTHREADS>>>(ids, emb, W, out, Tp1);
}

// round 11
// speedup vs baseline: 2.8270x; 2.8270x over previous
#include <cuda_runtime.h>
#include <cstdint>

#define D_MODEL 1024
#define NB 4
#define NCTA 128
#define NTHREADS 512          // 16 warps: 2 half-row warps per row, 8 rows
#define TP1_MAX 2049
#define BOS 0

typedef unsigned long long u64;

// Tagged hidden state: one 64-bit word per element = {tag:32 | value_bits:32}.
// Producer of h_t stores tag = t+1 in the SAME 8-byte scalar relaxed-atomic
// store as the value (single-copy atomic -> no tearing; proven R8).
// Double-buffered by t&1; dependency ordering bounds CTA skew (proven R8).
__device__ u64 g_hbuf2[2][NB][D_MODEL];

__global__ void rnn_init_kernel() {
    int i = blockIdx.x * blockDim.x + threadIdx.x;
    if (i < 2 * NB * D_MODEL)
        reinterpret_cast<u64*>(g_hbuf2)[i] = 0ull;   // tag 0 == h_{-1}
}

__device__ __forceinline__ u64 ld_relaxed_u64(const u64* p) {
    u64 v;
    asm volatile("ld.relaxed.gpu.global.u64 %0, [%1];" : "=l"(v) : "l"(p) : "memory");
    return v;
}
__device__ __forceinline__ void st_relaxed_u64(u64* p, u64 v) {
    asm volatile("st.relaxed.gpu.global.u64 [%0], %1;" :: "l"(p), "l"(v) : "memory");
}

// Persistent kernel: 128 CTAs x 8 rows, R8 skeleton (4-chain interleave,
// tagged-u64 protocol, ONE barrier per unit, publish->check distance ~3
// iterations) but with 512 threads: each row is computed by TWO half-column
// warps (s=0: cols 0-511, s=1: cols 512-1023) -> 4 warps/SMSP overlap the
// LDS/SHFL latency chains that starved R8's 2 warps/SMSP.
// The half combine is pipelined across the barrier: s=1 writes its half to
// psum before BAR; at the NEXT iteration s=0 lane0 reads psum, adds its own
// pending half + embedding, and publishes unit u-1 (tagged u64 + out).
__global__ void __launch_bounds__(NTHREADS, 1)
rnn_scan_kernel(const int*   __restrict__ ids,
                const float* __restrict__ emb,
                const float* __restrict__ W,
                float*       __restrict__ out,
                int Tp1)
{
    __shared__ unsigned short ids_sm[NB * TP1_MAX];  // tokens incl. BOS (vocab<65536)
    __shared__ float4 hsm[2][D_MODEL / 4];           // staged h (one unit), dbl-buf
    __shared__ float  psum[2][8];                    // s=1 half-sums, dbl-buf

    const int tid  = threadIdx.x;
    const int lane = tid & 31;
    const int w    = tid >> 5;
    const int s    = w >> 3;                         // column half
    const int wg   = w & 7;                          // row index in CTA
    const int row  = blockIdx.x * 8 + wg;

    // ---- W half-row -> registers: 16 floats/lane ----
    const float4* __restrict__ Wv = reinterpret_cast<const float4*>(W);
    float4 wr[4];
#pragma unroll
    for (int k = 0; k < 4; ++k)
        wr[k] = Wv[(size_t)row * 256 + s * 128 + lane + 32 * k];

    // ---- stage token ids with BOS prepended ----
    const int T = Tp1 - 1;
    for (int i = tid; i < NB * Tp1; i += NTHREADS) {
        int b = i / Tp1;
        int t = i - b * Tp1;
        ids_sm[i] = (unsigned short)((t == 0) ? BOS : ids[b * T + (t - 1)]);
    }
    if (tid < 256) hsm[0][tid] = make_float4(0.f, 0.f, 0.f, 0.f); // h_{-1}=0
    __syncthreads();

    // ---- embedding prefetch (s=0 lane0): statically-indexed per chain ----
    float e_cur[NB];
    const bool pub = (s == 0 && lane == 0);
    if (pub) {
#pragma unroll
        for (int b = 0; b < NB; ++b)
            e_cur[b] = emb[(size_t)ids_sm[b * Tp1] * D_MODEL + row];
    }

    float pend = 0.0f;                // s=0 lane0: own half of unit u-1's dot
    float2* const hw[2] = { reinterpret_cast<float2*>(hsm[0]),
                            reinterpret_cast<float2*>(hsm[1]) };

    for (int t = 0; t < Tp1; ++t) {
#pragma unroll
        for (int b = 0; b < NB; ++b) {
            // parities (static under unroll): unit u = 4t+b
            const int qcur = b & 1;                  // u & 1
            const int qprv = qcur ^ 1;               // (u-1) & 1

            // ---- A. publish unit u-1 = (tp, bp): pend + psum + emb ----
            if (pub && !(t == 0 && b == 0)) {
                const int bp = (b > 0) ? b - 1 : 3;
                const int tp = (b > 0) ? t : t - 1;
                float v = pend + psum[qprv][wg] + e_cur[bp];
                out[((size_t)bp * Tp1 + tp) * D_MODEL + row] = v;
                st_relaxed_u64(&g_hbuf2[tp & 1][bp][row],
                               ((u64)(unsigned)(tp + 1) << 32) |
                               (u64)__float_as_uint(v));
                if (tp + 1 < Tp1)    // prefetch e for (tp+1, bp), used 4 units later
                    e_cur[bp] = emb[(size_t)ids_sm[bp * Tp1 + tp + 1] * D_MODEL + row];
            }

            // ---- B. issue tagged stage loads for unit u+1's input ----
            // next unit: (t, b+1) if b<3 else (t+1, 0); its input h was
            // published ~2 iterations ago (unit u-3 publish happens at u-2).
            const int  bn = (b < 3) ? b + 1 : 0;
            const int  tn = (b < 3) ? t : t + 1;
            const bool have_next = (tn < Tp1);
            const u64* sp = nullptr;
            u64 s0v, s1v;
            const unsigned exp = (unsigned)tn;       // tag of h_{tn-1}
            if (have_next) {
                const int slot = (tn + 1) & 1;       // h_{tn-1} lives here
                sp  = &g_hbuf2[slot][bn][2 * tid];
                s0v = ld_relaxed_u64(sp + 0);
                s1v = ld_relaxed_u64(sp + 1);
            }

            // ---- C. half matvec: 512 cols, 16 FFMA, 2 accumulators ----
            const float4* __restrict__ h4 = hsm[qcur];
            float a0 = 0.f, a1 = 0.f;
            {
                float4 h0 = h4[s * 128 + lane +  0];
                float4 h1 = h4[s * 128 + lane + 32];
                float4 h2 = h4[s * 128 + lane + 64];
                float4 h3 = h4[s * 128 + lane + 96];
                a0 += wr[0].x * h0.x; a0 += wr[0].y * h0.y;
                a0 += wr[0].z * h0.z; a0 += wr[0].w * h0.w;
                a1 += wr[1].x * h1.x; a1 += wr[1].y * h1.y;
                a1 += wr[1].z * h1.z; a1 += wr[1].w * h1.w;
                a0 += wr[2].x * h2.x; a0 += wr[2].y * h2.y;
                a0 += wr[2].z * h2.z; a0 += wr[2].w * h2.w;
                a1 += wr[3].x * h3.x; a1 += wr[3].y * h3.y;
                a1 += wr[3].z * h3.z; a1 += wr[3].w * h3.w;
            }
            float a = a0 + a1;
#pragma unroll
            for (int off = 16; off > 0; off >>= 1)
                a += __shfl_xor_sync(0xffffffffu, a, off);

            // ---- D. save halves: s=0 keeps register, s=1 -> psum ----
            if (lane == 0) {
                if (s == 0) pend = a;
                else        psum[qcur][wg] = a;
            }

            // ---- E. tag check (the ONLY wait) + publish stage to smem ----
            if (have_next) {
                while ((unsigned)(s0v >> 32) != exp ||
                       (unsigned)(s1v >> 32) != exp) {
                    s0v = ld_relaxed_u64(sp + 0);
                    s1v = ld_relaxed_u64(sp + 1);
                }
                hw[qcur ^ 1][tid] = make_float2(__uint_as_float((unsigned)s0v),
                                                __uint_as_float((unsigned)s1v));
            }

            // ---- F. single barrier per unit ----
            __syncthreads();
        }
    }

    // ---- drain: publish the last unit (Tp1-1, 3) ----
    if (pub) {
        const int tp = Tp1 - 1, bp = 3;
        float v = pend + psum[(4 * tp + bp) & 1][wg] + e_cur[bp];
        out[((size_t)bp * Tp1 + tp) * D_MODEL + row] = v;
    }
}

extern "C" void kernel_launch(void* const* d_in, const int* in_sizes, int n_in,
                              void* d_out, int out_size) {
    const int*   ids = (const int*)d_in[0];
    const float* emb = (const float*)d_in[1];
    const float* W   = (const float*)d_in[2];
    float* out = (float*)d_out;

    int Tp1 = out_size / (NB * D_MODEL);   // 2049 for the reference shapes
    if (Tp1 > TP1_MAX) Tp1 = TP1_MAX;

    rnn_init_kernel<<<32, 256>>>();
    rnn_scan_kernel<<<NCTA, NTHREADS>>>(ids, emb, W, out, Tp1);
}